// round 6
// baseline (speedup 1.0000x reference)
#include <cuda_runtime.h>
#include <cstdint>

// HGN forward. Shapes fixed: U=I=100000, D=64, L=50, B=4096, T=100.
#define D 64
#define LSEQ 50
#define TPRED 100
#define BPB 4        // batches per block (main kernel)
#define PRE_BPB 16
#define BMAX 4096
#define NXF 7        // ceil(800/128) transfers per thread

__device__ float g_ubias[BMAX * D];    // u@fg_user_W + fub + fib
__device__ float g_ugu[BMAX * LSEQ];   // u@instance_gate_user

static __device__ __forceinline__ unsigned long long pk(float a, float b) {
    unsigned long long r;
    asm("mov.b64 %0, {%1, %2};" : "=l"(r) : "f"(a), "f"(b));
    return r;
}
static __device__ __forceinline__ void upk(unsigned long long v, float& a, float& b) {
    asm("mov.b64 {%0, %1}, %2;" : "=f"(a), "=f"(b) : "l"(v));
}
static __device__ __forceinline__ unsigned long long fma2(
    unsigned long long a, unsigned long long b, unsigned long long c) {
    unsigned long long r;
    asm("fma.rn.f32x2 %0, %1, %2, %3;" : "=l"(r) : "l"(a), "l"(b), "l"(c));
    return r;
}
static __device__ __forceinline__ float sum4(unsigned long long a, unsigned long long b) {
    float a0, a1, b0, b1;
    upk(a, a0, a1); upk(b, b0, b1);
    return (a0 + a1) + (b0 + b1);
}
static __device__ __forceinline__ float sigmoidf(float x) {
    return 1.0f / (1.0f + __expf(-x));
}
static __device__ __forceinline__ uint32_t smem_u32(const void* p) {
    uint32_t a;
    asm("{ .reg .u64 t; cvta.to.shared.u64 t, %1; cvt.u32.u64 %0, t; }" : "=r"(a) : "l"(p));
    return a;
}
static __device__ __forceinline__ void cp16(uint32_t dst, const void* src) {
    asm volatile("cp.async.cg.shared.global [%0], [%1], 16;" :: "r"(dst), "l"(src) : "memory");
}
#define CP_COMMIT() asm volatile("cp.async.commit_group;" ::: "memory")
#define CP_WAIT0()  asm volatile("cp.async.wait_group 0;" ::: "memory")

// ---------------------------------------------------------------------------
// Precompute: g_ubias[b][d] = u@fg_user_W + fub + fib ; g_ugu[b][l] = u@gu
// ---------------------------------------------------------------------------
__global__ __launch_bounds__(128) void hgn_pre(
    const int* __restrict__ user_ids, const float* __restrict__ user_tab,
    const float* __restrict__ fuW, const float* __restrict__ fub,
    const float* __restrict__ fib, const float* __restrict__ gu, int B)
{
    __shared__ __align__(16) float s_u[D];
    const int j = threadIdx.x;
    float wcol[D];
    float biasj = 0.0f;
    if (j < D) {
        #pragma unroll
        for (int k = 0; k < D; k++) wcol[k] = fuW[k * D + j];
        biasj = fub[j] + fib[j];
    } else if (j < D + LSEQ) {
        const int jj = j - D;
        #pragma unroll
        for (int k = 0; k < D; k++) wcol[k] = gu[k * LSEQ + jj];
    }
    const int b0 = blockIdx.x * PRE_BPB;
    for (int bb = 0; bb < PRE_BPB; bb++) {
        const int b = b0 + bb;
        if (b >= B) break;
        if (j < D) s_u[j] = user_tab[(size_t)user_ids[b] * D + j];
        __syncthreads();
        float acc = biasj;
        const float4* up = (const float4*)s_u;
        #pragma unroll
        for (int q = 0; q < D / 4; q++) {
            float4 r = up[q];
            acc += r.x * wcol[4*q] + r.y * wcol[4*q+1] + r.z * wcol[4*q+2] + r.w * wcol[4*q+3];
        }
        if (j < D)             g_ubias[b * D + j] = acc;
        else if (j < D + LSEQ) g_ugu[b * LSEQ + (j - D)] = acc;
        __syncthreads();
    }
}

// ---------------------------------------------------------------------------
// Main kernel: 128 threads, 2 K-split groups of 64. Software-pipelined item
// gather via cp.async into a single buffer (dead after combine phase).
// ---------------------------------------------------------------------------
__global__ __launch_bounds__(128, 5) void hgn_main(
    const int* __restrict__ item_seq,
    const int* __restrict__ user_ids,
    const int* __restrict__ items_pred,
    const float* __restrict__ user_tab,
    const float* __restrict__ item_tab,
    const float* __restrict__ fiW,
    const float* __restrict__ gi,
    const float* __restrict__ W2,
    const float* __restrict__ b2,
    float* __restrict__ out,
    int B)
{
    __shared__ __align__(16) float s_item[LSEQ][D];   // gather target (cp.async)
    __shared__ __align__(16) float s_pA[LSEQ][D];     // grp0 partials -> gated (in place)
    __shared__ __align__(16) float s_pB[LSEQ][D];     // grp1 partials
    __shared__ __align__(16) float s_v[D];
    __shared__ float s_score[LSEQ];
    __shared__ float s_isum[2][D];
    __shared__ float s_uo[2][D];
    __shared__ float s_ssum[2];
    __shared__ int s_idx[TPRED];

    const int tid  = threadIdx.x;
    const int d    = tid & 63;
    const int grp  = tid >> 6;
    const int lane = tid & 31;
    const int warp = tid >> 5;

    const uint32_t s_item_u32 = smem_u32(s_item);

    // Half a fg_item_W column register-resident: W[32*grp + kk][d].
    unsigned long long colp[16];
    #pragma unroll
    for (int k = 0; k < 16; k++) {
        float a = fiW[(32 * grp + 2 * k) * D + d];
        float c = fiW[(32 * grp + 2 * k + 1) * D + d];
        colp[k] = pk(a, c);
    }
    const float gi_lo = gi[lane];
    const float gi_hi = gi[lane + 32];

    const int bfirst = blockIdx.x * BPB;

    // --- pre-loop: gather batch bfirst's item rows via cp.async ---
    int nseq[NXF];
    if (bfirst < B) {
        #pragma unroll
        for (int i = 0; i < NXF; i++) {
            const int idx = tid + 128 * i;
            if (idx < LSEQ * 16) nseq[i] = item_seq[(size_t)bfirst * LSEQ + (idx >> 4)];
        }
        #pragma unroll
        for (int i = 0; i < NXF; i++) {
            const int idx = tid + 128 * i;
            if (idx < LSEQ * 16)
                cp16(s_item_u32 + (uint32_t)idx * 16,
                     item_tab + (size_t)nseq[i] * D + (idx & 15) * 4);
        }
        CP_COMMIT();
    }

    for (int bb = 0; bb < BPB; bb++) {
        const int b = bfirst + bb;
        if (b >= B) break;
        const int bn = b + 1;
        const bool havenext = (bb + 1 < BPB) && (bn < B);

        // --- phase 1: independent loads + wait for gather ---
        const float bias = g_ubias[b * D + d];
        const float u    = user_tab[(size_t)user_ids[b] * D + d];
        if (havenext) {
            #pragma unroll
            for (int i = 0; i < NXF; i++) {
                const int idx = tid + 128 * i;
                if (idx < LSEQ * 16) nseq[i] = item_seq[(size_t)bn * LSEQ + (idx >> 4)];
            }
        }
        CP_WAIT0();
        __syncthreads();

        // --- phase 2: gating GEMM partials (this group's K-half, all rows) ---
        float (*pout)[D] = grp ? s_pB : s_pA;
        for (int l = 0; l < LSEQ; l += 2) {
            unsigned long long a0 = pk(0.f, 0.f), a1 = pk(0.f, 0.f);
            unsigned long long c0 = pk(0.f, 0.f), c1 = pk(0.f, 0.f);
            const float4* r0 = (const float4*)&s_item[l][grp * 32];
            const float4* r1 = (const float4*)&s_item[l + 1][grp * 32];
            #pragma unroll
            for (int q = 0; q < 8; q++) {
                float4 x = r0[q];
                a0 = fma2(pk(x.x, x.y), colp[2 * q + 0], a0);
                a1 = fma2(pk(x.z, x.w), colp[2 * q + 1], a1);
                float4 y = r1[q];
                c0 = fma2(pk(y.x, y.y), colp[2 * q + 0], c0);
                c1 = fma2(pk(y.z, y.w), colp[2 * q + 1], c1);
            }
            pout[l][d]     = sum4(a0, a1);
            pout[l + 1][d] = sum4(c0, c1);
        }
        __syncthreads();

        // --- phase 3: combine + sigmoid gate (in place into s_pA); item sum ---
        float isum_p = 0.0f;
        {
            const int l0 = grp * 25;
            #pragma unroll 5
            for (int l = l0; l < l0 + 25; l++) {
                const float logit = s_pA[l][d] + s_pB[l][d] + bias;
                const float val   = s_item[l][d];
                s_pA[l][d] = val * sigmoidf(logit);
                isum_p += val;
            }
        }
        s_isum[grp][d] = isum_p;
        __syncthreads();      // item buffer now dead -> safe to refill

        // --- phase 4: issue next gather; stage pred idx; instance gating ---
        if (havenext) {
            #pragma unroll
            for (int i = 0; i < NXF; i++) {
                const int idx = tid + 128 * i;
                if (idx < LSEQ * 16)
                    cp16(s_item_u32 + (uint32_t)idx * 16,
                         item_tab + (size_t)nseq[i] * D + (idx & 15) * 4);
            }
            CP_COMMIT();
        }
        if (tid < TPRED) s_idx[tid] = items_pred[(size_t)b * TPRED + tid];
        for (int l = warp; l < LSEQ; l += 4) {
            float p = s_pA[l][lane] * gi_lo + s_pA[l][lane + 32] * gi_hi;
            p += __shfl_xor_sync(0xffffffffu, p, 16);
            p += __shfl_xor_sync(0xffffffffu, p, 8);
            p += __shfl_xor_sync(0xffffffffu, p, 4);
            p += __shfl_xor_sync(0xffffffffu, p, 2);
            p += __shfl_xor_sync(0xffffffffu, p, 1);
            if (lane == 0) s_score[l] = sigmoidf(p + g_ugu[b * LSEQ + l]);
        }
        __syncthreads();

        // --- phase 5: union partials + v ---
        float ssum_p = 0.0f, uo_p = 0.0f;
        {
            const int l0 = grp * 25;
            #pragma unroll 5
            for (int l = l0; l < l0 + 25; l++) {
                const float sc = s_score[l];
                ssum_p += sc;
                uo_p += s_pA[l][d] * sc;
            }
        }
        s_uo[grp][d] = uo_p;
        if (d == 0) s_ssum[grp] = ssum_p;
        __syncthreads();
        if (grp == 0) {
            const float ssum = s_ssum[0] + s_ssum[1];
            s_v[d] = u + s_isum[0][d] + s_isum[1][d]
                   + (s_uo[0][d] + s_uo[1][d]) / ssum;
        }
        __syncthreads();

        // --- phase 6: scoring, 4 warps x 4 outputs/iter ---
        {
            const int g4 = lane >> 3;
            const int gl = lane & 7;
            const float4 va = *(const float4*)&s_v[gl * 8];
            const float4 vb = *(const float4*)&s_v[gl * 8 + 4];
            float* outp = out + (size_t)b * TPRED;
            #pragma unroll
            for (int i = 0; i < 7; i++) {
                const int t = warp * 4 + g4 + 16 * i;
                const int tt = (t < TPRED) ? t : 0;
                const int it = s_idx[tt];
                const float4* rowp = (const float4*)(W2 + (size_t)it * D);
                const float4 a = rowp[gl * 2];
                const float4 c = rowp[gl * 2 + 1];
                float p = a.x * va.x + a.y * va.y + a.z * va.z + a.w * va.w
                        + c.x * vb.x + c.y * vb.y + c.z * vb.z + c.w * vb.w;
                p += __shfl_xor_sync(0xffffffffu, p, 1);
                p += __shfl_xor_sync(0xffffffffu, p, 2);
                p += __shfl_xor_sync(0xffffffffu, p, 4);
                if (t < TPRED && gl == 0) outp[t] = p + b2[it];
            }
        }
        // no trailing barrier: next iteration's top barrier separates hazards
    }
}

// ---------------------------------------------------------------------------
// Harness entry. Inputs (metadata order):
//  0 item_seq[B,L] i32   1 user_ids[B] i32      2 items_to_predict[B,T] i32
//  3 user_emb[U,D] f32   4 item_emb[I,D] f32
//  5 fg_item_W[D,D]      6 fg_item_b[D]         7 fg_user_W[D,D]   8 fg_user_b[D]
//  9 instance_gate_item[D,1]  10 instance_gate_user[D,L]
// 11 W2_table[I,D]      12 b2_table[I,1]
// Output: res[B,T] f32
// ---------------------------------------------------------------------------
extern "C" void kernel_launch(void* const* d_in, const int* in_sizes, int n_in,
                              void* d_out, int out_size)
{
    const int*   item_seq   = (const int*)d_in[0];
    const int*   user_ids   = (const int*)d_in[1];
    const int*   items_pred = (const int*)d_in[2];
    const float* user_tab   = (const float*)d_in[3];
    const float* item_tab   = (const float*)d_in[4];
    const float* fiW        = (const float*)d_in[5];
    const float* fib        = (const float*)d_in[6];
    const float* fuW        = (const float*)d_in[7];
    const float* fub        = (const float*)d_in[8];
    const float* gi         = (const float*)d_in[9];
    const float* gu         = (const float*)d_in[10];
    const float* W2         = (const float*)d_in[11];
    const float* b2         = (const float*)d_in[12];
    float*       out        = (float*)d_out;

    const int B = in_sizes[1];

    const int pre_grid  = (B + PRE_BPB - 1) / PRE_BPB;
    const int main_grid = (B + BPB - 1) / BPB;

    hgn_pre<<<pre_grid, 128>>>(user_ids, user_tab, fuW, fub, fib, gu, B);
    hgn_main<<<main_grid, 128>>>(item_seq, user_ids, items_pred,
                                 user_tab, item_tab, fiW, gi, W2, b2, out, B);
}

// round 7
// speedup vs baseline: 1.2133x; 1.2133x over previous
#include <cuda_runtime.h>
#include <cstdint>

// HGN forward. Shapes fixed: U=I=100000, D=64, L=50, B=4096, T=100.
#define D 64
#define LSEQ 50
#define TPRED 100
#define BPB 2        // batches per block (main kernel)
#define PRE_BPB 4
#define BMAX 4096

__device__ float g_ubias[BMAX * D];    // u@fg_user_W + fub + fib
__device__ float g_ugu[BMAX * LSEQ];   // u@instance_gate_user

static __device__ __forceinline__ unsigned long long pk(float a, float b) {
    unsigned long long r;
    asm("mov.b64 %0, {%1, %2};" : "=l"(r) : "f"(a), "f"(b));
    return r;
}
static __device__ __forceinline__ void upk(unsigned long long v, float& a, float& b) {
    asm("mov.b64 {%0, %1}, %2;" : "=f"(a), "=f"(b) : "l"(v));
}
static __device__ __forceinline__ unsigned long long fma2(
    unsigned long long a, unsigned long long b, unsigned long long c) {
    unsigned long long r;
    asm("fma.rn.f32x2 %0, %1, %2, %3;" : "=l"(r) : "l"(a), "l"(b), "l"(c));
    return r;
}
static __device__ __forceinline__ float sum4(unsigned long long a, unsigned long long b) {
    float a0, a1, b0, b1;
    upk(a, a0, a1); upk(b, b0, b1);
    return (a0 + a1) + (b0 + b1);
}
static __device__ __forceinline__ float sigmoidf(float x) {
    return 1.0f / (1.0f + __expf(-x));
}

// ---------------------------------------------------------------------------
// Precompute: g_ubias[b][d] = u@fg_user_W + fub + fib ; g_ugu[b][l] = u@gu
// ---------------------------------------------------------------------------
__global__ __launch_bounds__(128) void hgn_pre(
    const int* __restrict__ user_ids, const float* __restrict__ user_tab,
    const float* __restrict__ fuW, const float* __restrict__ fub,
    const float* __restrict__ fib, const float* __restrict__ gu, int B)
{
    __shared__ __align__(16) float s_u[D];
    const int j = threadIdx.x;
    float wcol[D];
    float biasj = 0.0f;
    if (j < D) {
        #pragma unroll
        for (int k = 0; k < D; k++) wcol[k] = fuW[k * D + j];
        biasj = fub[j] + fib[j];
    } else if (j < D + LSEQ) {
        const int jj = j - D;
        #pragma unroll
        for (int k = 0; k < D; k++) wcol[k] = gu[k * LSEQ + jj];
    }
    const int b0 = blockIdx.x * PRE_BPB;
    for (int bb = 0; bb < PRE_BPB; bb++) {
        const int b = b0 + bb;
        if (b >= B) break;
        if (j < D) s_u[j] = user_tab[(size_t)user_ids[b] * D + j];
        __syncthreads();
        float acc = biasj;
        const float4* up = (const float4*)s_u;
        #pragma unroll
        for (int q = 0; q < D / 4; q++) {
            float4 r = up[q];
            acc += r.x * wcol[4*q] + r.y * wcol[4*q+1] + r.z * wcol[4*q+2] + r.w * wcol[4*q+3];
        }
        if (j < D)             g_ubias[b * D + j] = acc;
        else if (j < D + LSEQ) g_ugu[b * LSEQ + (j - D)] = acc;
        __syncthreads();
    }
}

// ---------------------------------------------------------------------------
// Main kernel: 128 threads, 2 K-split groups of 64, target 8 blocks/SM.
// Gating GEMM in two 25-row subtiles sharing one partial-buffer pair; gated
// values overwrite s_item in place (item values folded into isum first).
// ---------------------------------------------------------------------------
__global__ __launch_bounds__(128, 8) void hgn_main(
    const int* __restrict__ item_seq,
    const int* __restrict__ user_ids,
    const int* __restrict__ items_pred,
    const float* __restrict__ user_tab,
    const float* __restrict__ item_tab,
    const float* __restrict__ fiW,
    const float* __restrict__ gi,
    const float* __restrict__ W2,
    const float* __restrict__ b2,
    float* __restrict__ out,
    int B)
{
    __shared__ __align__(16) float s_item[LSEQ][D];   // item rows -> gated (in place)
    __shared__ __align__(16) float s_p[2][25][D];     // K-split partials (one subtile)
    __shared__ __align__(16) float s_v[D];
    __shared__ float s_score[LSEQ];
    __shared__ float s_isum[2][D];
    __shared__ float s_uo[2][D];
    __shared__ float s_ssum[2];
    __shared__ int s_idx[TPRED];

    const int tid  = threadIdx.x;
    const int d    = tid & 63;
    const int grp  = tid >> 6;
    const int lane = tid & 31;
    const int warp = tid >> 5;

    // Half a fg_item_W column register-resident: W[32*grp + kk][d].
    unsigned long long colp[16];
    #pragma unroll
    for (int k = 0; k < 16; k++) {
        float a = fiW[(32 * grp + 2 * k) * D + d];
        float c = fiW[(32 * grp + 2 * k + 1) * D + d];
        colp[k] = pk(a, c);
    }
    const float gi_lo = gi[lane];
    const float gi_hi = gi[lane + 32];

    for (int bb = 0; bb < BPB; bb++) {
        const int b = blockIdx.x * BPB + bb;
        if (b >= B) break;

        // --- gather item rows (16 threads share one seq index -> LDG bcast) ---
        #pragma unroll
        for (int i = 0; i < 7; i++) {
            const int idx = tid + 128 * i;
            if (idx < LSEQ * 16) {
                const int rl = idx >> 4, q = idx & 15;
                const int it = __ldg(&item_seq[(size_t)b * LSEQ + rl]);
                ((float4*)s_item[rl])[q] =
                    ((const float4*)(item_tab + (size_t)it * D))[q];
            }
        }
        const float bias = g_ubias[b * D + d];
        const float u    = user_tab[(size_t)user_ids[b] * D + d];
        __syncthreads();

        // --- gating GEMM + combine, two 25-row subtiles ---
        float isum_p = 0.0f;
        #pragma unroll
        for (int sub = 0; sub < 2; sub++) {
            const int l0 = sub * 25;
            // partials: this group's K-half, rows l0..l0+24
            for (int li = 0; li < 24; li += 2) {
                const int l = l0 + li;
                unsigned long long a0 = pk(0.f, 0.f), a1 = pk(0.f, 0.f);
                unsigned long long c0 = pk(0.f, 0.f), c1 = pk(0.f, 0.f);
                const float4* r0 = (const float4*)&s_item[l][grp * 32];
                const float4* r1 = (const float4*)&s_item[l + 1][grp * 32];
                #pragma unroll
                for (int q = 0; q < 8; q++) {
                    float4 x = r0[q];
                    a0 = fma2(pk(x.x, x.y), colp[2 * q + 0], a0);
                    a1 = fma2(pk(x.z, x.w), colp[2 * q + 1], a1);
                    float4 y = r1[q];
                    c0 = fma2(pk(y.x, y.y), colp[2 * q + 0], c0);
                    c1 = fma2(pk(y.z, y.w), colp[2 * q + 1], c1);
                }
                s_p[grp][li][d]     = sum4(a0, a1);
                s_p[grp][li + 1][d] = sum4(c0, c1);
            }
            {   // last row of subtile (25th)
                const int l = l0 + 24;
                unsigned long long a0 = pk(0.f, 0.f), a1 = pk(0.f, 0.f);
                const float4* r0 = (const float4*)&s_item[l][grp * 32];
                #pragma unroll
                for (int q = 0; q < 8; q++) {
                    float4 x = r0[q];
                    a0 = fma2(pk(x.x, x.y), colp[2 * q + 0], a0);
                    a1 = fma2(pk(x.z, x.w), colp[2 * q + 1], a1);
                }
                s_p[grp][24][d] = sum4(a0, a1);
            }
            __syncthreads();
            // combine + sigmoid gate, in place; row-parity split across groups
            #pragma unroll
            for (int i = 0; i < 13; i++) {
                const int li = 2 * i + grp;
                if (li < 25) {
                    const int l = l0 + li;
                    const float logit = s_p[0][li][d] + s_p[1][li][d] + bias;
                    const float val   = s_item[l][d];
                    s_item[l][d] = val * sigmoidf(logit);
                    isum_p += val;
                }
            }
            __syncthreads();
        }
        s_isum[grp][d] = isum_p;

        // --- instance gating (4 warps over 50 rows) + stage pred indices ---
        if (tid < TPRED) s_idx[tid] = items_pred[(size_t)b * TPRED + tid];
        for (int l = warp; l < LSEQ; l += 4) {
            float p = s_item[l][lane] * gi_lo + s_item[l][lane + 32] * gi_hi;
            p += __shfl_xor_sync(0xffffffffu, p, 16);
            p += __shfl_xor_sync(0xffffffffu, p, 8);
            p += __shfl_xor_sync(0xffffffffu, p, 4);
            p += __shfl_xor_sync(0xffffffffu, p, 2);
            p += __shfl_xor_sync(0xffffffffu, p, 1);
            if (lane == 0) s_score[l] = sigmoidf(p + g_ugu[b * LSEQ + l]);
        }
        __syncthreads();

        // --- union partials + v ---
        float ssum_p = 0.0f, uo_p = 0.0f;
        {
            const int l0 = grp * 25;
            #pragma unroll 5
            for (int l = l0; l < l0 + 25; l++) {
                const float sc = s_score[l];
                ssum_p += sc;
                uo_p += s_item[l][d] * sc;
            }
        }
        s_uo[grp][d] = uo_p;
        if (d == 0) s_ssum[grp] = ssum_p;
        __syncthreads();
        if (grp == 0) {
            const float ssum = s_ssum[0] + s_ssum[1];
            s_v[d] = u + s_isum[0][d] + s_isum[1][d]
                   + (s_uo[0][d] + s_uo[1][d]) / ssum;
        }
        __syncthreads();

        // --- scoring: 4 warps x 4 outputs/iter over 100 outputs ---
        {
            const int g4 = lane >> 3;
            const int gl = lane & 7;
            const float4 va = *(const float4*)&s_v[gl * 8];
            const float4 vb = *(const float4*)&s_v[gl * 8 + 4];
            float* outp = out + (size_t)b * TPRED;
            #pragma unroll
            for (int i = 0; i < 7; i++) {
                const int t = warp * 4 + g4 + 16 * i;
                const int tt = (t < TPRED) ? t : 0;
                const int it = s_idx[tt];
                const float4* rowp = (const float4*)(W2 + (size_t)it * D);
                const float4 a = rowp[gl * 2];
                const float4 c = rowp[gl * 2 + 1];
                float p = a.x * va.x + a.y * va.y + a.z * va.z + a.w * va.w
                        + c.x * vb.x + c.y * vb.y + c.z * vb.z + c.w * vb.w;
                p += __shfl_xor_sync(0xffffffffu, p, 1);
                p += __shfl_xor_sync(0xffffffffu, p, 2);
                p += __shfl_xor_sync(0xffffffffu, p, 4);
                if (t < TPRED && gl == 0) outp[t] = p + b2[it];
            }
        }
        __syncthreads();   // protect smem reuse for next batch
    }
}

// ---------------------------------------------------------------------------
// Harness entry. Inputs (metadata order):
//  0 item_seq[B,L] i32   1 user_ids[B] i32      2 items_to_predict[B,T] i32
//  3 user_emb[U,D] f32   4 item_emb[I,D] f32
//  5 fg_item_W[D,D]      6 fg_item_b[D]         7 fg_user_W[D,D]   8 fg_user_b[D]
//  9 instance_gate_item[D,1]  10 instance_gate_user[D,L]
// 11 W2_table[I,D]      12 b2_table[I,1]
// Output: res[B,T] f32
// ---------------------------------------------------------------------------
extern "C" void kernel_launch(void* const* d_in, const int* in_sizes, int n_in,
                              void* d_out, int out_size)
{
    const int*   item_seq   = (const int*)d_in[0];
    const int*   user_ids   = (const int*)d_in[1];
    const int*   items_pred = (const int*)d_in[2];
    const float* user_tab   = (const float*)d_in[3];
    const float* item_tab   = (const float*)d_in[4];
    const float* fiW        = (const float*)d_in[5];
    const float* fib        = (const float*)d_in[6];
    const float* fuW        = (const float*)d_in[7];
    const float* fub        = (const float*)d_in[8];
    const float* gi         = (const float*)d_in[9];
    const float* gu         = (const float*)d_in[10];
    const float* W2         = (const float*)d_in[11];
    const float* b2         = (const float*)d_in[12];
    float*       out        = (float*)d_out;

    const int B = in_sizes[1];

    const int pre_grid  = (B + PRE_BPB - 1) / PRE_BPB;
    const int main_grid = (B + BPB - 1) / BPB;

    hgn_pre<<<pre_grid, 128>>>(user_ids, user_tab, fuW, fub, fib, gu, B);
    hgn_main<<<main_grid, 128>>>(item_seq, user_ids, items_pred,
                                 user_tab, item_tab, fiW, gi, W2, b2, out, B);
}

// round 8
// speedup vs baseline: 1.3690x; 1.1283x over previous
#include <cuda_runtime.h>
#include <cstdint>

// HGN forward. Shapes fixed: U=I=100000, D=64, L=50, B=4096, T=100.
#define D 64
#define LSEQ 50
#define TPRED 100
#define BPB 2
#define PRE_BPB 4
#define BMAX 4096
#define SUBMAX 13

typedef unsigned long long u64;

__device__ float g_ubias[BMAX * D];    // u@fg_user_W + fub + fib
__device__ float g_ugu[BMAX * LSEQ];   // u@instance_gate_user

static __device__ __forceinline__ u64 pk(float a, float b) {
    u64 r;
    asm("mov.b64 %0, {%1, %2};" : "=l"(r) : "f"(a), "f"(b));
    return r;
}
static __device__ __forceinline__ void upk(u64 v, float& a, float& b) {
    asm("mov.b64 {%0, %1}, %2;" : "=f"(a), "=f"(b) : "l"(v));
}
static __device__ __forceinline__ u64 fma2(u64 a, u64 b, u64 c) {
    u64 r;
    asm("fma.rn.f32x2 %0, %1, %2, %3;" : "=l"(r) : "l"(a), "l"(b), "l"(c));
    return r;
}
static __device__ __forceinline__ u64 add2(u64 a, u64 b) {
    u64 r;
    asm("add.rn.f32x2 %0, %1, %2;" : "=l"(r) : "l"(a), "l"(b));
    return r;
}
static __device__ __forceinline__ float sigmoidf(float x) {
    return 1.0f / (1.0f + __expf(-x));
}

// ---------------------------------------------------------------------------
// Precompute: g_ubias[b][d] = u@fg_user_W + fub + fib ; g_ugu[b][l] = u@gu
// ---------------------------------------------------------------------------
__global__ __launch_bounds__(128) void hgn_pre(
    const int* __restrict__ user_ids, const float* __restrict__ user_tab,
    const float* __restrict__ fuW, const float* __restrict__ fub,
    const float* __restrict__ fib, const float* __restrict__ gu, int B)
{
    __shared__ __align__(16) float s_u[D];
    const int j = threadIdx.x;
    float wcol[D];
    float biasj = 0.0f;
    if (j < D) {
        #pragma unroll
        for (int k = 0; k < D; k++) wcol[k] = fuW[k * D + j];
        biasj = fub[j] + fib[j];
    } else if (j < D + LSEQ) {
        const int jj = j - D;
        #pragma unroll
        for (int k = 0; k < D; k++) wcol[k] = gu[k * LSEQ + jj];
    }
    const int b0 = blockIdx.x * PRE_BPB;
    for (int bb = 0; bb < PRE_BPB; bb++) {
        const int b = b0 + bb;
        if (b >= B) break;
        if (j < D) s_u[j] = user_tab[(size_t)user_ids[b] * D + j];
        __syncthreads();
        float acc = biasj;
        const float4* up = (const float4*)s_u;
        #pragma unroll
        for (int q = 0; q < D / 4; q++) {
            float4 r = up[q];
            acc += r.x * wcol[4*q] + r.y * wcol[4*q+1] + r.z * wcol[4*q+2] + r.w * wcol[4*q+3];
        }
        if (j < D)             g_ubias[b * D + j] = acc;
        else if (j < D + LSEQ) g_ugu[b * LSEQ + (j - D)] = acc;
        __syncthreads();
    }
}

// ---------------------------------------------------------------------------
// Main kernel: 128 threads = 4 warps. Warp w owns K-quarter [16w,16w+16);
// lane owns column pair (d=lane, d=lane+32) with packed f32x2 weights.
// Gated output overwrites s_item rows in packed (d,d+32) order:
//   gated(d) at s_item[l][2*(d&31) + (d>>5)].
// ---------------------------------------------------------------------------
__global__ __launch_bounds__(128, 8) void hgn_main(
    const int* __restrict__ item_seq,
    const int* __restrict__ user_ids,
    const int* __restrict__ items_pred,
    const float* __restrict__ user_tab,
    const float* __restrict__ item_tab,
    const float* __restrict__ fiW,
    const float* __restrict__ gi,
    const float* __restrict__ W2,
    const float* __restrict__ b2,
    float* __restrict__ out,
    int B)
{
    __shared__ __align__(16) float s_item[LSEQ][D];     // items -> gated (packed, in place)
    __shared__ __align__(16) u64 s_pp[4][SUBMAX][32];   // per-warp K-quarter partials
    __shared__ __align__(16) u64 s_isump[4][32];        // per-warp packed item sums
    __shared__ __align__(16) float s_v[D];
    __shared__ float s_score[LSEQ];
    __shared__ int s_idx[TPRED];

    const int tid  = threadIdx.x;
    const int lane = tid & 31;
    const int w    = tid >> 5;       // warp = K-quarter

    // Packed weight quarter: colp[j] = (fiW[16w+j][lane], fiW[16w+j][lane+32])
    u64 colp[16];
    #pragma unroll
    for (int j = 0; j < 16; j++) {
        colp[j] = pk(fiW[(16 * w + j) * D + lane],
                     fiW[(16 * w + j) * D + lane + 32]);
    }
    const float gi_lo = gi[lane];
    const float gi_hi = gi[lane + 32];

    const int SUB0[5] = {0, 13, 26, 38, 50};

    for (int bb = 0; bb < BPB; bb++) {
        const int b = blockIdx.x * BPB + bb;
        if (b >= B) break;

        // --- gather item rows (16 threads share one seq index -> LDG bcast) ---
        #pragma unroll
        for (int i = 0; i < 7; i++) {
            const int idx = tid + 128 * i;
            if (idx < LSEQ * 16) {
                const int rl = idx >> 4, q = idx & 15;
                const int it = __ldg(&item_seq[(size_t)b * LSEQ + rl]);
                ((float4*)s_item[rl])[q] =
                    ((const float4*)(item_tab + (size_t)it * D))[q];
            }
        }
        const float biasA = g_ubias[b * D + lane];
        const float biasB = g_ubias[b * D + lane + 32];
        const float uemb  = (tid < D)
            ? user_tab[(size_t)user_ids[b] * D + tid] : 0.0f;
        __syncthreads();

        // --- gating GEMM + combine in row subtiles ---
        u64 isum2 = pk(0.f, 0.f);
        #pragma unroll
        for (int s = 0; s < 4; s++) {
            const int l0 = SUB0[s], l1 = SUB0[s + 1];
            // GEMM: this warp's K-quarter, packed (d, d+32) accumulators
            int l = l0;
            for (; l + 1 < l1; l += 2) {
                u64 a0 = pk(0.f, 0.f), a1 = pk(0.f, 0.f);
                u64 c0 = pk(0.f, 0.f), c1 = pk(0.f, 0.f);
                const float4* r0 = (const float4*)&s_item[l][16 * w];
                const float4* r1 = (const float4*)&s_item[l + 1][16 * w];
                #pragma unroll
                for (int q = 0; q < 4; q++) {
                    const float4 x = r0[q];
                    a0 = fma2(pk(x.x, x.x), colp[4*q+0], a0);
                    a1 = fma2(pk(x.y, x.y), colp[4*q+1], a1);
                    a0 = fma2(pk(x.z, x.z), colp[4*q+2], a0);
                    a1 = fma2(pk(x.w, x.w), colp[4*q+3], a1);
                    const float4 y = r1[q];
                    c0 = fma2(pk(y.x, y.x), colp[4*q+0], c0);
                    c1 = fma2(pk(y.y, y.y), colp[4*q+1], c1);
                    c0 = fma2(pk(y.z, y.z), colp[4*q+2], c0);
                    c1 = fma2(pk(y.w, y.w), colp[4*q+3], c1);
                }
                s_pp[w][l - l0][lane]     = add2(a0, a1);
                s_pp[w][l + 1 - l0][lane] = add2(c0, c1);
            }
            if (l < l1) {
                u64 a0 = pk(0.f, 0.f), a1 = pk(0.f, 0.f);
                const float4* r0 = (const float4*)&s_item[l][16 * w];
                #pragma unroll
                for (int q = 0; q < 4; q++) {
                    const float4 x = r0[q];
                    a0 = fma2(pk(x.x, x.x), colp[4*q+0], a0);
                    a1 = fma2(pk(x.y, x.y), colp[4*q+1], a1);
                    a0 = fma2(pk(x.z, x.z), colp[4*q+2], a0);
                    a1 = fma2(pk(x.w, x.w), colp[4*q+3], a1);
                }
                s_pp[w][l - l0][lane] = add2(a0, a1);
            }
            __syncthreads();
            // combine: rows strided over warps; gate in place (packed layout)
            for (int lc = l0 + w; lc < l1; lc += 4) {
                const float itA = s_item[lc][lane];
                const float itB = s_item[lc][lane + 32];
                const u64 p = add2(add2(s_pp[0][lc - l0][lane], s_pp[1][lc - l0][lane]),
                                   add2(s_pp[2][lc - l0][lane], s_pp[3][lc - l0][lane]));
                float pA, pB;
                upk(p, pA, pB);
                const float gA = itA * sigmoidf(pA + biasA);
                const float gB = itB * sigmoidf(pB + biasB);
                isum2 = add2(isum2, pk(itA, itB));
                __syncwarp();
                ((float2*)s_item[lc])[lane] = make_float2(gA, gB);
            }
            __syncthreads();
        }
        s_isump[w][lane] = isum2;

        // --- instance gating (packed LDS.64 per row) + stage pred indices ---
        if (tid < TPRED) s_idx[tid] = items_pred[(size_t)b * TPRED + tid];
        for (int l = w; l < LSEQ; l += 4) {
            const float2 g = ((const float2*)s_item[l])[lane];
            float p = g.x * gi_lo + g.y * gi_hi;
            p += __shfl_xor_sync(0xffffffffu, p, 16);
            p += __shfl_xor_sync(0xffffffffu, p, 8);
            p += __shfl_xor_sync(0xffffffffu, p, 4);
            p += __shfl_xor_sync(0xffffffffu, p, 2);
            p += __shfl_xor_sync(0xffffffffu, p, 1);
            if (lane == 0) s_score[l] = sigmoidf(p + g_ugu[b * LSEQ + l]);
        }
        __syncthreads();

        // --- union + v (2 warps; d = tid) ---
        if (tid < D) {
            const int j = tid & 31, half = tid >> 5;
            float ssum = 0.0f, uo = 0.0f;
            #pragma unroll 5
            for (int l = 0; l < LSEQ; l++) {
                const float sc = s_score[l];
                ssum += sc;
                uo += s_item[l][2 * j + half] * sc;
            }
            const u64 is4 = add2(add2(s_isump[0][j], s_isump[1][j]),
                                 add2(s_isump[2][j], s_isump[3][j]));
            float isA, isB;
            upk(is4, isA, isB);
            s_v[tid] = uemb + (half ? isB : isA) + uo / ssum;
        }
        __syncthreads();

        // --- scoring: 4 warps x 4 outputs/iter over 100 outputs ---
        {
            const int g4 = lane >> 3;
            const int gl = lane & 7;
            const float4 va = *(const float4*)&s_v[gl * 8];
            const float4 vb = *(const float4*)&s_v[gl * 8 + 4];
            float* outp = out + (size_t)b * TPRED;
            #pragma unroll
            for (int i = 0; i < 7; i++) {
                const int t = w * 4 + g4 + 16 * i;
                const int tt = (t < TPRED) ? t : 0;
                const int it = s_idx[tt];
                const float4* rowp = (const float4*)(W2 + (size_t)it * D);
                const float4 a = rowp[gl * 2];
                const float4 c = rowp[gl * 2 + 1];
                float p = a.x * va.x + a.y * va.y + a.z * va.z + a.w * va.w
                        + c.x * vb.x + c.y * vb.y + c.z * vb.z + c.w * vb.w;
                p += __shfl_xor_sync(0xffffffffu, p, 1);
                p += __shfl_xor_sync(0xffffffffu, p, 2);
                p += __shfl_xor_sync(0xffffffffu, p, 4);
                if (t < TPRED && gl == 0) outp[t] = p + b2[it];
            }
        }
        __syncthreads();   // protect smem reuse for next batch
    }
}

// ---------------------------------------------------------------------------
// Harness entry. Inputs (metadata order):
//  0 item_seq[B,L] i32   1 user_ids[B] i32      2 items_to_predict[B,T] i32
//  3 user_emb[U,D] f32   4 item_emb[I,D] f32
//  5 fg_item_W[D,D]      6 fg_item_b[D]         7 fg_user_W[D,D]   8 fg_user_b[D]
//  9 instance_gate_item[D,1]  10 instance_gate_user[D,L]
// 11 W2_table[I,D]      12 b2_table[I,1]
// Output: res[B,T] f32
// ---------------------------------------------------------------------------
extern "C" void kernel_launch(void* const* d_in, const int* in_sizes, int n_in,
                              void* d_out, int out_size)
{
    const int*   item_seq   = (const int*)d_in[0];
    const int*   user_ids   = (const int*)d_in[1];
    const int*   items_pred = (const int*)d_in[2];
    const float* user_tab   = (const float*)d_in[3];
    const float* item_tab   = (const float*)d_in[4];
    const float* fiW        = (const float*)d_in[5];
    const float* fib        = (const float*)d_in[6];
    const float* fuW        = (const float*)d_in[7];
    const float* fub        = (const float*)d_in[8];
    const float* gi         = (const float*)d_in[9];
    const float* gu         = (const float*)d_in[10];
    const float* W2         = (const float*)d_in[11];
    const float* b2         = (const float*)d_in[12];
    float*       out        = (float*)d_out;

    const int B = in_sizes[1];

    const int pre_grid  = (B + PRE_BPB - 1) / PRE_BPB;
    const int main_grid = (B + BPB - 1) / BPB;

    hgn_pre<<<pre_grid, 128>>>(user_ids, user_tab, fuW, fub, fib, gu, B);
    hgn_main<<<main_grid, 128>>>(item_seq, user_ids, items_pred,
                                 user_tab, item_tab, fiW, gi, W2, b2, out, B);
}

// round 9
// speedup vs baseline: 1.5229x; 1.1124x over previous
#include <cuda_runtime.h>
#include <cstdint>

// HGN forward. Shapes fixed: U=I=100000, D=64, L=50, B=4096, T=100.
#define D 64
#define LSEQ 50
#define TPRED 100
#define PRE_BPB 4
#define BMAX 4096
#define SUBMAX 13

typedef unsigned long long u64;

__device__ float g_ubias[BMAX * D];    // u@fg_user_W + fub + fib
__device__ float g_ugu[BMAX * LSEQ];   // u@instance_gate_user

static __device__ __forceinline__ u64 pk(float a, float b) {
    u64 r;
    asm("mov.b64 %0, {%1, %2};" : "=l"(r) : "f"(a), "f"(b));
    return r;
}
static __device__ __forceinline__ void upk(u64 v, float& a, float& b) {
    asm("mov.b64 {%0, %1}, %2;" : "=f"(a), "=f"(b) : "l"(v));
}
static __device__ __forceinline__ u64 fma2(u64 a, u64 b, u64 c) {
    u64 r;
    asm("fma.rn.f32x2 %0, %1, %2, %3;" : "=l"(r) : "l"(a), "l"(b), "l"(c));
    return r;
}
static __device__ __forceinline__ u64 add2(u64 a, u64 b) {
    u64 r;
    asm("add.rn.f32x2 %0, %1, %2;" : "=l"(r) : "l"(a), "l"(b));
    return r;
}
static __device__ __forceinline__ float sigmoidf(float x) {
    return 1.0f / (1.0f + __expf(-x));
}

// ---------------------------------------------------------------------------
// Precompute: g_ubias[b][d] = u@fg_user_W + fub + fib ; g_ugu[b][l] = u@gu
// ---------------------------------------------------------------------------
__global__ __launch_bounds__(128) void hgn_pre(
    const int* __restrict__ user_ids, const float* __restrict__ user_tab,
    const float* __restrict__ fuW, const float* __restrict__ fub,
    const float* __restrict__ fib, const float* __restrict__ gu, int B)
{
    __shared__ __align__(16) float s_u[D];
    const int j = threadIdx.x;
    float wcol[D];
    float biasj = 0.0f;
    if (j < D) {
        #pragma unroll
        for (int k = 0; k < D; k++) wcol[k] = fuW[k * D + j];
        biasj = fub[j] + fib[j];
    } else if (j < D + LSEQ) {
        const int jj = j - D;
        #pragma unroll
        for (int k = 0; k < D; k++) wcol[k] = gu[k * LSEQ + jj];
    }
    const int b0 = blockIdx.x * PRE_BPB;
    for (int bb = 0; bb < PRE_BPB; bb++) {
        const int b = b0 + bb;
        if (b >= B) break;
        if (j < D) s_u[j] = user_tab[(size_t)user_ids[b] * D + j];
        __syncthreads();
        float acc = biasj;
        const float4* up = (const float4*)s_u;
        #pragma unroll
        for (int q = 0; q < D / 4; q++) {
            float4 r = up[q];
            acc += r.x * wcol[4*q] + r.y * wcol[4*q+1] + r.z * wcol[4*q+2] + r.w * wcol[4*q+3];
        }
        if (j < D)             g_ubias[b * D + j] = acc;
        else if (j < D + LSEQ) g_ugu[b * LSEQ + (j - D)] = acc;
        __syncthreads();
    }
}

// ---------------------------------------------------------------------------
// Main kernel: one batch per 128-thread block, 4 warps = 4 K-quarters.
// Lane owns column pair (d=lane, d=lane+32); packed f32x2 weights in regs.
// Instance score fused into the combine pass (warp holds the full gated row).
// Gated values overwrite s_item rows in packed (d,d+32) order:
//   gated(d) at s_item[l][2*(d&31) + (d>>5)].
// ---------------------------------------------------------------------------
__global__ __launch_bounds__(128, 8) void hgn_main(
    const int* __restrict__ item_seq,
    const int* __restrict__ user_ids,
    const int* __restrict__ items_pred,
    const float* __restrict__ user_tab,
    const float* __restrict__ item_tab,
    const float* __restrict__ fiW,
    const float* __restrict__ gi,
    const float* __restrict__ W2,
    const float* __restrict__ b2,
    float* __restrict__ out,
    int B)
{
    __shared__ __align__(16) float s_item[LSEQ][D];     // items -> gated (packed, in place)
    __shared__ __align__(16) u64 s_pp[4][SUBMAX][32];   // per-warp K-quarter partials
    __shared__ __align__(16) u64 s_isump[4][32];        // per-warp packed item sums
    __shared__ __align__(16) float s_v[D];
    __shared__ float s_score[LSEQ];
    __shared__ int s_idx[TPRED];

    const int tid  = threadIdx.x;
    const int lane = tid & 31;
    const int w    = tid >> 5;       // warp = K-quarter
    const int b    = blockIdx.x;
    if (b >= B) return;

    // Packed weight quarter: colp[j] = (fiW[16w+j][lane], fiW[16w+j][lane+32])
    u64 colp[16];
    #pragma unroll
    for (int j = 0; j < 16; j++) {
        colp[j] = pk(fiW[(16 * w + j) * D + lane],
                     fiW[(16 * w + j) * D + lane + 32]);
    }
    const float gi_lo = gi[lane];
    const float gi_hi = gi[lane + 32];

    // --- gather item rows (16 threads share one seq index -> LDG bcast);
    //     stage prediction indices in the same phase ---
    #pragma unroll
    for (int i = 0; i < 7; i++) {
        const int idx = tid + 128 * i;
        if (idx < LSEQ * 16) {
            const int rl = idx >> 4, q = idx & 15;
            const int it = __ldg(&item_seq[(size_t)b * LSEQ + rl]);
            ((float4*)s_item[rl])[q] =
                ((const float4*)(item_tab + (size_t)it * D))[q];
        }
    }
    if (tid < TPRED) s_idx[tid] = items_pred[(size_t)b * TPRED + tid];
    const float biasA = g_ubias[b * D + lane];
    const float biasB = g_ubias[b * D + lane + 32];
    const float uemb  = (tid < D) ? user_tab[(size_t)user_ids[b] * D + tid] : 0.0f;
    __syncthreads();

    // --- gating GEMM + fused combine/instance-score, 4 row subtiles ---
    const int SUB0[5] = {0, 13, 26, 38, 50};
    u64 isum2 = pk(0.f, 0.f);
    #pragma unroll
    for (int s = 0; s < 4; s++) {
        const int l0 = SUB0[s], l1 = SUB0[s + 1];
        // GEMM: this warp's K-quarter, packed (d, d+32) accumulators
        int l = l0;
        for (; l + 1 < l1; l += 2) {
            u64 a0 = pk(0.f, 0.f), a1 = pk(0.f, 0.f);
            u64 c0 = pk(0.f, 0.f), c1 = pk(0.f, 0.f);
            const float4* r0 = (const float4*)&s_item[l][16 * w];
            const float4* r1 = (const float4*)&s_item[l + 1][16 * w];
            #pragma unroll
            for (int q = 0; q < 4; q++) {
                const float4 x = r0[q];
                a0 = fma2(pk(x.x, x.x), colp[4*q+0], a0);
                a1 = fma2(pk(x.y, x.y), colp[4*q+1], a1);
                a0 = fma2(pk(x.z, x.z), colp[4*q+2], a0);
                a1 = fma2(pk(x.w, x.w), colp[4*q+3], a1);
                const float4 y = r1[q];
                c0 = fma2(pk(y.x, y.x), colp[4*q+0], c0);
                c1 = fma2(pk(y.y, y.y), colp[4*q+1], c1);
                c0 = fma2(pk(y.z, y.z), colp[4*q+2], c0);
                c1 = fma2(pk(y.w, y.w), colp[4*q+3], c1);
            }
            s_pp[w][l - l0][lane]     = add2(a0, a1);
            s_pp[w][l + 1 - l0][lane] = add2(c0, c1);
        }
        if (l < l1) {
            u64 a0 = pk(0.f, 0.f), a1 = pk(0.f, 0.f);
            const float4* r0 = (const float4*)&s_item[l][16 * w];
            #pragma unroll
            for (int q = 0; q < 4; q++) {
                const float4 x = r0[q];
                a0 = fma2(pk(x.x, x.x), colp[4*q+0], a0);
                a1 = fma2(pk(x.y, x.y), colp[4*q+1], a1);
                a0 = fma2(pk(x.z, x.z), colp[4*q+2], a0);
                a1 = fma2(pk(x.w, x.w), colp[4*q+3], a1);
            }
            s_pp[w][l - l0][lane] = add2(a0, a1);
        }
        __syncthreads();
        // combine + gate + instance score, rows strided over warps
        for (int lc = l0 + w; lc < l1; lc += 4) {
            const float ug = g_ugu[b * LSEQ + lc];         // early, independent
            const float itA = s_item[lc][lane];
            const float itB = s_item[lc][lane + 32];
            const u64 p = add2(add2(s_pp[0][lc - l0][lane], s_pp[1][lc - l0][lane]),
                               add2(s_pp[2][lc - l0][lane], s_pp[3][lc - l0][lane]));
            float pA, pB;
            upk(p, pA, pB);
            const float gA = itA * sigmoidf(pA + biasA);
            const float gB = itB * sigmoidf(pB + biasB);
            isum2 = add2(isum2, pk(itA, itB));
            // instance-gate dot: full warp holds the row
            float sp = gA * gi_lo + gB * gi_hi;
            sp += __shfl_xor_sync(0xffffffffu, sp, 16);
            sp += __shfl_xor_sync(0xffffffffu, sp, 8);
            sp += __shfl_xor_sync(0xffffffffu, sp, 4);
            sp += __shfl_xor_sync(0xffffffffu, sp, 2);
            sp += __shfl_xor_sync(0xffffffffu, sp, 1);
            if (lane == 0) s_score[lc] = sigmoidf(sp + ug);
            __syncwarp();
            ((float2*)s_item[lc])[lane] = make_float2(gA, gB);
        }
        if (s == 3) s_isump[w][lane] = isum2;
        __syncthreads();
    }

    // --- prefetch scoring iter 0 (covers union latency) ---
    const int g4 = lane >> 3;
    const int gl = lane & 7;
    const int t0 = w * 4 + g4;
    const int it0 = s_idx[t0];
    const float4* row0 = (const float4*)(W2 + (size_t)it0 * D);
    const float4 pa = row0[gl * 2];
    const float4 pc = row0[gl * 2 + 1];
    const float pb2 = b2[it0];

    // --- union + v (64 threads) ---
    if (tid < D) {
        const int j = tid & 31, half = tid >> 5;
        float ssum = 0.0f, uo = 0.0f;
        #pragma unroll 5
        for (int l = 0; l < LSEQ; l++) {
            const float sc = s_score[l];
            ssum += sc;
            uo += s_item[l][2 * j + half] * sc;
        }
        const u64 is4 = add2(add2(s_isump[0][j], s_isump[1][j]),
                             add2(s_isump[2][j], s_isump[3][j]));
        float isA, isB;
        upk(is4, isA, isB);
        s_v[tid] = uemb + (half ? isB : isA) + uo / ssum;
    }
    __syncthreads();

    // --- scoring: 4 warps x 4 outputs/iter over 100 outputs ---
    {
        const float4 va = *(const float4*)&s_v[gl * 8];
        const float4 vb = *(const float4*)&s_v[gl * 8 + 4];
        float* outp = out + (size_t)b * TPRED;
        // iter 0 from prefetched registers
        {
            float p = pa.x * va.x + pa.y * va.y + pa.z * va.z + pa.w * va.w
                    + pc.x * vb.x + pc.y * vb.y + pc.z * vb.z + pc.w * vb.w;
            p += __shfl_xor_sync(0xffffffffu, p, 1);
            p += __shfl_xor_sync(0xffffffffu, p, 2);
            p += __shfl_xor_sync(0xffffffffu, p, 4);
            if (gl == 0) outp[t0] = p + pb2;
        }
        #pragma unroll
        for (int i = 1; i < 7; i++) {
            const int t = w * 4 + g4 + 16 * i;
            const int tt = (t < TPRED) ? t : 0;
            const int it = s_idx[tt];
            const float4* rowp = (const float4*)(W2 + (size_t)it * D);
            const float4 a = rowp[gl * 2];
            const float4 c = rowp[gl * 2 + 1];
            float p = a.x * va.x + a.y * va.y + a.z * va.z + a.w * va.w
                    + c.x * vb.x + c.y * vb.y + c.z * vb.z + c.w * vb.w;
            p += __shfl_xor_sync(0xffffffffu, p, 1);
            p += __shfl_xor_sync(0xffffffffu, p, 2);
            p += __shfl_xor_sync(0xffffffffu, p, 4);
            if (t < TPRED && gl == 0) outp[t] = p + b2[it];
        }
    }
}

// ---------------------------------------------------------------------------
// Harness entry. Inputs (metadata order):
//  0 item_seq[B,L] i32   1 user_ids[B] i32      2 items_to_predict[B,T] i32
//  3 user_emb[U,D] f32   4 item_emb[I,D] f32
//  5 fg_item_W[D,D]      6 fg_item_b[D]         7 fg_user_W[D,D]   8 fg_user_b[D]
//  9 instance_gate_item[D,1]  10 instance_gate_user[D,L]
// 11 W2_table[I,D]      12 b2_table[I,1]
// Output: res[B,T] f32
// ---------------------------------------------------------------------------
extern "C" void kernel_launch(void* const* d_in, const int* in_sizes, int n_in,
                              void* d_out, int out_size)
{
    const int*   item_seq   = (const int*)d_in[0];
    const int*   user_ids   = (const int*)d_in[1];
    const int*   items_pred = (const int*)d_in[2];
    const float* user_tab   = (const float*)d_in[3];
    const float* item_tab   = (const float*)d_in[4];
    const float* fiW        = (const float*)d_in[5];
    const float* fib        = (const float*)d_in[6];
    const float* fuW        = (const float*)d_in[7];
    const float* fub        = (const float*)d_in[8];
    const float* gi         = (const float*)d_in[9];
    const float* gu         = (const float*)d_in[10];
    const float* W2         = (const float*)d_in[11];
    const float* b2         = (const float*)d_in[12];
    float*       out        = (float*)d_out;

    const int B = in_sizes[1];

    const int pre_grid = (B + PRE_BPB - 1) / PRE_BPB;

    hgn_pre<<<pre_grid, 128>>>(user_ids, user_tab, fuW, fub, fib, gu, B);
    hgn_main<<<B, 128>>>(item_seq, user_ids, items_pred,
                         user_tab, item_tab, fiW, gi, W2, b2, out, B);
}